// round 9
// baseline (speedup 1.0000x reference)
#include <cuda_runtime.h>
#include <cuda_fp16.h>
#include <stdint.h>

// Problem constants
#define CB 2
#define CL 2048
#define CD 1024
#define CH 16
#define CDK 64

constexpr int  BHn        = CB * CH;               // 32
constexpr long PROJ_ELEMS = (long)CB * CL * CD;    // 4,194,304
constexpr long S_ELEMS    = (long)BHn * CL * CL;   // 134,217,728
constexpr long ZN         = (long)BHn * CL;        // 65,536

// uint8 E encoding: e = exp(s), s in [-0.1253, 0.1253] -> e in [0.8824, 1.1335]
#define ELO    0.87f
#define EINV   910.7142857f        // 255 / 0.28
#define ESTEP  0.001098039216f     // 0.28 / 255
#define EMAGIC 8388608.0f          // 2^23

// Scratch (static device globals -- no runtime allocation)
__device__ __half  g_Qh[PROJ_ELEMS];               // Q proj -> normalized, fp16
__device__ __half  g_Kh[PROJ_ELEMS];               // K proj -> normalized, fp16
__device__ __half  g_Vh[PROJ_ELEMS];               // V projection, fp16
__device__ uint8_t g_E8[S_ELEMS];                  // exp(scores), uint8 affine code
__device__ float   g_invZ[ZN];

// ---------------------------------------------------------------------------
// helpers
// ---------------------------------------------------------------------------
__device__ __forceinline__ void mma16h(float* d, const uint32_t* a, const uint32_t* b) {
    asm volatile(
        "mma.sync.aligned.m16n8k16.row.col.f32.f16.f16.f32 "
        "{%0,%1,%2,%3}, {%4,%5,%6,%7}, {%8,%9}, {%0,%1,%2,%3};"
        : "+f"(d[0]), "+f"(d[1]), "+f"(d[2]), "+f"(d[3])
        : "r"(a[0]), "r"(a[1]), "r"(a[2]), "r"(a[3]), "r"(b[0]), "r"(b[1]));
}

__device__ __forceinline__ uint32_t sptr(const void* p) {
    return (uint32_t)__cvta_generic_to_shared(p);
}

__device__ __forceinline__ void ldm4(uint32_t* a, uint32_t addr) {
    asm volatile("ldmatrix.sync.aligned.m8n8.x4.shared.b16 {%0,%1,%2,%3}, [%4];"
                 : "=r"(a[0]), "=r"(a[1]), "=r"(a[2]), "=r"(a[3]) : "r"(addr));
}

__device__ __forceinline__ void ldm4t(uint32_t* a, uint32_t addr) {
    asm volatile("ldmatrix.sync.aligned.m8n8.x4.trans.shared.b16 {%0,%1,%2,%3}, [%4];"
                 : "=r"(a[0]), "=r"(a[1]), "=r"(a[2]), "=r"(a[3]) : "r"(addr));
}

// ---------------------------------------------------------------------------
// fp16-MMA NT projection GEMM: C[m,n] = half( sum_k A[m,k]*B[n,k] )
// BM=64, BN=128, BK=32, 256 threads (2x4 warps), ldmatrix, fp32 accum.
// ---------------------------------------------------------------------------
__global__ __launch_bounds__(256) void proj_h_kernel(
    const float* __restrict__ A, const float* __restrict__ B,
    __half* __restrict__ C)
{
    __shared__ __half As[64][40];
    __shared__ __half Bs[128][40];

    const float* Ab = A + (long)blockIdx.y * 64 * CD;
    const float* Bb = B + (long)blockIdx.x * 128 * CD;

    const int tid  = threadIdx.x;
    const int w    = tid >> 5, lane = tid & 31;
    const int wm   = w >> 2, wn = w & 3;
    const int g    = lane >> 2, tig = lane & 3;

    float acc[2][4][4];
    #pragma unroll
    for (int i = 0; i < 2; i++)
        #pragma unroll
        for (int j = 0; j < 4; j++)
            #pragma unroll
            for (int r = 0; r < 4; r++) acc[i][j][r] = 0.f;

    float4 pa[2], pb[4];
    #pragma unroll
    for (int j = 0; j < 2; j++) {
        int s = tid + 256 * j;
        pa[j] = *(const float4*)(Ab + (long)(s >> 3) * CD + (s & 7) * 4);
    }
    #pragma unroll
    for (int j = 0; j < 4; j++) {
        int s = tid + 256 * j;
        pb[j] = *(const float4*)(Bb + (long)(s >> 3) * CD + (s & 7) * 4);
    }

    for (int k0 = 0; k0 < CD; k0 += 32) {
        #pragma unroll
        for (int j = 0; j < 2; j++) {
            int s = tid + 256 * j;
            int r = s >> 3, c = (s & 7) * 4;
            As[r][c + 0] = __float2half(pa[j].x);
            As[r][c + 1] = __float2half(pa[j].y);
            As[r][c + 2] = __float2half(pa[j].z);
            As[r][c + 3] = __float2half(pa[j].w);
        }
        #pragma unroll
        for (int j = 0; j < 4; j++) {
            int s = tid + 256 * j;
            int r = s >> 3, c = (s & 7) * 4;
            Bs[r][c + 0] = __float2half(pb[j].x);
            Bs[r][c + 1] = __float2half(pb[j].y);
            Bs[r][c + 2] = __float2half(pb[j].z);
            Bs[r][c + 3] = __float2half(pb[j].w);
        }
        __syncthreads();

        if (k0 + 32 < CD) {
            #pragma unroll
            for (int j = 0; j < 2; j++) {
                int s = tid + 256 * j;
                pa[j] = *(const float4*)(Ab + (long)(s >> 3) * CD + k0 + 32 + (s & 7) * 4);
            }
            #pragma unroll
            for (int j = 0; j < 4; j++) {
                int s = tid + 256 * j;
                pb[j] = *(const float4*)(Bb + (long)(s >> 3) * CD + k0 + 32 + (s & 7) * 4);
            }
        }

        #pragma unroll
        for (int ks = 0; ks < 2; ks++) {
            const int c0 = ks * 16;
            uint32_t af[2][4], bf[4][2];
            #pragma unroll
            for (int mt = 0; mt < 2; mt++)
                ldm4(af[mt], sptr(&As[wm * 32 + mt * 16 + (lane & 15)][c0 + (lane >> 4) * 8]));
            #pragma unroll
            for (int nh = 0; nh < 2; nh++) {
                uint32_t r4[4];
                ldm4(r4, sptr(&Bs[wn * 32 + nh * 16 + (lane & 15)][c0 + (lane >> 4) * 8]));
                bf[2 * nh][0]     = r4[0]; bf[2 * nh][1]     = r4[2];
                bf[2 * nh + 1][0] = r4[1]; bf[2 * nh + 1][1] = r4[3];
            }
            #pragma unroll
            for (int mt = 0; mt < 2; mt++)
                #pragma unroll
                for (int nt = 0; nt < 4; nt++)
                    mma16h(acc[mt][nt], af[mt], bf[nt]);
        }
        __syncthreads();
    }

    __half* Cb = C + (long)blockIdx.y * 64 * CD + (long)blockIdx.x * 128;
    #pragma unroll
    for (int mt = 0; mt < 2; mt++)
        #pragma unroll
        for (int nt = 0; nt < 4; nt++) {
            long r0  = wm * 32 + mt * 16 + g;
            int  col = wn * 32 + nt * 8 + 2 * tig;
            *(__half2*)&Cb[r0 * CD + col] =
                __floats2half2_rn(acc[mt][nt][0], acc[mt][nt][1]);
            *(__half2*)&Cb[(r0 + 8) * CD + col] =
                __floats2half2_rn(acc[mt][nt][2], acc[mt][nt][3]);
        }
}

// ---------------------------------------------------------------------------
// In-place L2 normalize of each 64-half segment; one warp per segment.
// blockIdx.y selects tensor: 0 -> Q (coef 0.125), 1 -> K (coef 1).
// ---------------------------------------------------------------------------
__global__ __launch_bounds__(256) void l2norm_h_kernel(__half* __restrict__ Q,
                                                       __half* __restrict__ K)
{
    __half* X = blockIdx.y ? K : Q;
    const float coef = blockIdx.y ? 1.0f : 0.125f;
    const int seg  = blockIdx.x * 8 + (threadIdx.x >> 5);
    const int lane = threadIdx.x & 31;
    __half2* p = (__half2*)(X + (long)seg * 64) + lane;
    float2 u = __half22float2(*p);
    float ss = u.x * u.x + u.y * u.y;
    #pragma unroll
    for (int o = 16; o; o >>= 1) ss += __shfl_xor_sync(0xffffffffu, ss, o);
    const float s = coef / fmaxf(sqrtf(ss), 1e-12f);
    *p = __floats2half2_rn(u.x * s, u.y * s);
}

// ---------------------------------------------------------------------------
// Fused flash attention (no-max softmax; scores bounded by 1/8):
// per (b,h,128-q tile): loop 64-k tiles: S=Q.K^T (fp16 MMA), E=exp(S) ->
// uint8-coded gmem (for avg) + fp16 register repack -> O += E.V (fp16 MMA),
// Z += rowsum(E).  Epilogue: out = O/Z, invZ stored for avg pass.
// 256 threads = 8 warps, each warp owns 16 q rows.  grid (CL/128, BHn).
// ---------------------------------------------------------------------------
__global__ __launch_bounds__(256) void flash_kernel(
    const __half* __restrict__ Qh, const __half* __restrict__ Kh,
    const __half* __restrict__ Vh, uint8_t* __restrict__ E8,
    float* __restrict__ invZ, float* __restrict__ out)
{
    __shared__ __half Qs[128][72];
    __shared__ __half Ks[64][72];
    __shared__ __half Vs[64][72];

    const int z = blockIdx.y, b = z >> 4, h = z & 15;
    const int qbase = blockIdx.x * 128;
    const int tid = threadIdx.x, w = tid >> 5, lane = tid & 31;
    const int g = lane >> 2, tig = lane & 3;

    // stage Q tile, pull per-warp A fragments (held for the whole kernel)
    const __half* Qg = Qh + ((long)b * CL + qbase) * CD + h * 64;
    #pragma unroll
    for (int j = 0; j < 4; j++) {
        int f = tid + 256 * j;
        int r = f >> 3, c = (f & 7) * 8;
        *(uint4*)&Qs[r][c] = *(const uint4*)(Qg + (long)r * CD + c);
    }
    __syncthreads();
    uint32_t aq[4][4];
    #pragma unroll
    for (int kc = 0; kc < 4; kc++)
        ldm4(aq[kc], sptr(&Qs[w * 16 + (lane & 15)][kc * 16 + (lane >> 4) * 8]));

    const __half* Kg = Kh + (long)b * CL * CD + h * 64;
    const __half* Vg = Vh + (long)b * CL * CD + h * 64;

    float acc_o[8][4];
    #pragma unroll
    for (int i = 0; i < 8; i++)
        #pragma unroll
        for (int r = 0; r < 4; r++) acc_o[i][r] = 0.f;
    float zr0 = 0.f, zr1 = 0.f;

    uint4 pk[2], pv[2];
    #pragma unroll
    for (int j = 0; j < 2; j++) {
        int f = tid + 256 * j;
        int r = f >> 3, c = (f & 7) * 8;
        pk[j] = *(const uint4*)(Kg + (long)r * CD + c);
        pv[j] = *(const uint4*)(Vg + (long)r * CD + c);
    }

    uint8_t* Eb = E8 + (long)z * CL * CL + (long)(qbase + w * 16 + g) * CL;

    for (int kt = 0; kt < CL / 64; kt++) {
        #pragma unroll
        for (int j = 0; j < 2; j++) {
            int f = tid + 256 * j;
            int r = f >> 3, c = (f & 7) * 8;
            *(uint4*)&Ks[r][c] = pk[j];
            *(uint4*)&Vs[r][c] = pv[j];
        }
        __syncthreads();

        if (kt + 1 < CL / 64) {
            #pragma unroll
            for (int j = 0; j < 2; j++) {
                int f = tid + 256 * j;
                int r = f >> 3, c = (f & 7) * 8;
                long row = (long)((kt + 1) * 64 + r);
                pk[j] = *(const uint4*)(Kg + row * CD + c);
                pv[j] = *(const uint4*)(Vg + row * CD + c);
            }
        }

        // scores: S[16q x 64k] per warp
        float s[8][4];
        #pragma unroll
        for (int i = 0; i < 8; i++)
            #pragma unroll
            for (int r = 0; r < 4; r++) s[i][r] = 0.f;

        #pragma unroll
        for (int kc = 0; kc < 4; kc++) {
            #pragma unroll
            for (int p = 0; p < 4; p++) {
                uint32_t r4[4];
                ldm4(r4, sptr(&Ks[p * 16 + (lane & 15)][kc * 16 + (lane >> 4) * 8]));
                uint32_t b0[2] = {r4[0], r4[2]}, b1[2] = {r4[1], r4[3]};
                mma16h(s[2 * p],     aq[kc], b0);
                mma16h(s[2 * p + 1], aq[kc], b1);
            }
        }

        // exp + fp16 repack (for PV) + uint8 encode -> gmem + row sums
        uint32_t ehlo[8], ehhi[8];
        #pragma unroll
        for (int nt = 0; nt < 8; nt++) {
            float e0 = __expf(s[nt][0]);
            float e1 = __expf(s[nt][1]);
            float e2 = __expf(s[nt][2]);
            float e3 = __expf(s[nt][3]);
            __half2 lo = __floats2half2_rn(e0, e1);
            __half2 hi = __floats2half2_rn(e2, e3);
            ehlo[nt] = *(uint32_t*)&lo;
            ehhi[nt] = *(uint32_t*)&hi;
            zr0 += e0 + e1;
            zr1 += e2 + e3;
            // uint8 affine encode via 2^23 magic add (no F2I)
            uint32_t f0 = __float_as_uint(fmaf(e0 - ELO, EINV, EMAGIC));
            uint32_t f1 = __float_as_uint(fmaf(e1 - ELO, EINV, EMAGIC));
            uint32_t f2 = __float_as_uint(fmaf(e2 - ELO, EINV, EMAGIC));
            uint32_t f3 = __float_as_uint(fmaf(e3 - ELO, EINV, EMAGIC));
            uint8_t* p0 = Eb + kt * 64 + nt * 8 + 2 * tig;
            *(unsigned short*)p0 =
                (unsigned short)__byte_perm(f0, f1, 0x0040);
            *(unsigned short*)(p0 + 8 * CL) =
                (unsigned short)__byte_perm(f2, f3, 0x0040);
        }

        // PV: O += E . V  (B via ldmatrix.trans on V[k][n])
        #pragma unroll
        for (int kc = 0; kc < 4; kc++) {
            uint32_t a[4] = {ehlo[2 * kc], ehhi[2 * kc], ehlo[2 * kc + 1], ehhi[2 * kc + 1]};
            #pragma unroll
            for (int p = 0; p < 4; p++) {
                uint32_t r4[4];
                ldm4t(r4, sptr(&Vs[kc * 16 + (lane & 15)][p * 16 + (lane >> 4) * 8]));
                uint32_t b0[2] = {r4[0], r4[1]}, b1[2] = {r4[2], r4[3]};
                mma16h(acc_o[2 * p],     a, b0);
                mma16h(acc_o[2 * p + 1], a, b1);
            }
        }
        __syncthreads();
    }

    // row sums across the 4 tig lanes (fixed order), then normalize + write
    zr0 += __shfl_xor_sync(0xffffffffu, zr0, 1);
    zr0 += __shfl_xor_sync(0xffffffffu, zr0, 2);
    zr1 += __shfl_xor_sync(0xffffffffu, zr1, 1);
    zr1 += __shfl_xor_sync(0xffffffffu, zr1, 2);
    const float iz0 = 1.0f / zr0;
    const float iz1 = 1.0f / zr1;
    if (tig == 0) {
        invZ[(long)z * CL + qbase + w * 16 + g]     = iz0;
        invZ[(long)z * CL + qbase + w * 16 + g + 8] = iz1;
    }
    float* Ob = out + (long)z * CL * CDK + (long)(qbase + w * 16) * CDK;
    #pragma unroll
    for (int nt = 0; nt < 8; nt++) {
        int col = nt * 8 + 2 * tig;
        *(float2*)&Ob[(long)g * CDK + col] =
            make_float2(acc_o[nt][0] * iz0, acc_o[nt][1] * iz0);
        *(float2*)&Ob[(long)(g + 8) * CDK + col] =
            make_float2(acc_o[nt][2] * iz1, acc_o[nt][3] * iz1);
    }
}

// ---------------------------------------------------------------------------
// avg[b,q,k] = (1/16) * sum_h invZ_h * (ELO + enc*ESTEP).  Block per (b,q),
// thread t covers cols t*8..t*8+7 (uint2 loads of uint8 codes).
// Decode: PRMT byte into 2^23 mantissa, subtract 2^23 per element (avoids
// catastrophic cancellation of the folded-constant form).
// ---------------------------------------------------------------------------
__global__ __launch_bounds__(256) void avg_kernel(const uint8_t* __restrict__ E8,
                                                  const float* __restrict__ invZ,
                                                  float* __restrict__ avg)
{
    const int b = blockIdx.x >> 11, q = blockIdx.x & 2047;
    const int t = threadIdx.x;
    __shared__ float wz[16];
    if (t < 16)
        wz[t] = invZ[(long)(b * 16 + t) * CL + q] * (1.0f / 16.0f);
    __syncthreads();

    float W = 0.f;
    #pragma unroll
    for (int h = 0; h < 16; h++) W += wz[h];

    float A[8];
    #pragma unroll
    for (int i = 0; i < 8; i++) A[i] = 0.f;

    #pragma unroll
    for (int h = 0; h < 16; h++) {
        const uint8_t* row = E8 + ((long)(b * 16 + h) * CL + q) * CL + t * 8;
        const float wh = wz[h];
        uint2 u = *(const uint2*)row;
        #pragma unroll
        for (int k = 0; k < 4; k++) {
            float f0 = __uint_as_float(__byte_perm(u.x, 0x4B000000u, 0x7440 + k));
            float f1 = __uint_as_float(__byte_perm(u.y, 0x4B000000u, 0x7440 + k));
            A[k]     = fmaf(wh, f0 - EMAGIC, A[k]);
            A[4 + k] = fmaf(wh, f1 - EMAGIC, A[4 + k]);
        }
    }

    const float C = ELO * W;
    float* arow = avg + ((long)b * CL + q) * CL + t * 8;
    *(float4*)arow = make_float4(fmaf(ESTEP, A[0], C), fmaf(ESTEP, A[1], C),
                                 fmaf(ESTEP, A[2], C), fmaf(ESTEP, A[3], C));
    *(float4*)(arow + 4) = make_float4(fmaf(ESTEP, A[4], C), fmaf(ESTEP, A[5], C),
                                       fmaf(ESTEP, A[6], C), fmaf(ESTEP, A[7], C));
}

// ---------------------------------------------------------------------------
extern "C" void kernel_launch(void* const* d_in, const int* in_sizes, int n_in,
                              void* d_out, int out_size)
{
    const float* q  = (const float*)d_in[0];
    const float* k  = (const float*)d_in[1];
    const float* v  = (const float*)d_in[2];
    const float* wq = (const float*)d_in[3];
    const float* wk = (const float*)d_in[4];
    const float* wv = (const float*)d_in[5];

    float* out = (float*)d_out;                        // [B,H,L,64]
    float* avg = out + (long)CB * CH * CL * CDK;       // [B,L,L]

    float   *iZ;
    __half  *Qh, *Kh, *Vh;
    uint8_t *Ep;
    cudaGetSymbolAddress((void**)&Qh, g_Qh);
    cudaGetSymbolAddress((void**)&Kh, g_Kh);
    cudaGetSymbolAddress((void**)&Vh, g_Vh);
    cudaGetSymbolAddress((void**)&Ep, g_E8);
    cudaGetSymbolAddress((void**)&iZ, g_invZ);

    // 1) Projections (fp16 MMA, fp32 accumulate, fp16 out)
    dim3 pg(CD / 128, (CB * CL) / 64, 1);
    proj_h_kernel<<<pg, 256>>>(q, wq, Qh);
    proj_h_kernel<<<pg, 256>>>(k, wk, Kh);
    proj_h_kernel<<<pg, 256>>>(v, wv, Vh);

    // 2) In-place L2 normalize Q (fold 1/8) and K in one launch
    dim3 ng((CB * CL * CH) / 8, 2);
    l2norm_h_kernel<<<ng, 256>>>(Qh, Kh);

    // 3) Fused attention: E (uint8) + invZ + out
    dim3 fg(CL / 128, BHn);
    flash_kernel<<<fg, 256>>>(Qh, Kh, Vh, Ep, iZ, out);

    // 4) attn_avg from uint8 E and invZ
    avg_kernel<<<CB * CL, 256>>>(Ep, iZ, avg);
}